// round 12
// baseline (speedup 1.0000x reference)
#include <cuda_runtime.h>
#include <cuda_bf16.h>
#include <cooperative_groups.h>
#include <cstdint>

namespace cg = cooperative_groups;

#define S_LEN 2048
#define B_N   64
#define W5    50
#define E_N   128
#define H_N   256
#define G_N   1024

typedef unsigned long long ull;

// ---------------- static device scratch (allocation-free) ----------------
__device__ float g_emb[(size_t)S_LEN * B_N * E_N];      // [s][b][e]
__device__ float g_xg [(size_t)S_LEN * B_N * G_N];      // [s][b][g]
__device__ float g_hs [(size_t)S_LEN * 16 * H_N * 4];   // [s][cl][j][b4]

__device__ __forceinline__ float sigf(float x) { return 1.0f / (1.0f + __expf(-x)); }
__device__ __forceinline__ float tanhf_fast(float x) {
    float e = __expf(2.0f * x);
    return 1.0f - 2.0f / (e + 1.0f);   // safe at +/-inf
}

// =============== Phase 1a: emb = relu(pw @ Wemb^T + bemb) ===============
__global__ void __launch_bounds__(256) emb_kernel(const float* __restrict__ pw,
                                                  const float* __restrict__ Wemb,
                                                  const float* __restrict__ bemb) {
    __shared__ float pw_s[64 * 51];
    __shared__ float we_s[128 * 51];
    const int s = blockIdx.x;
    const int t = threadIdx.x;

    for (int i = t; i < 64 * 50; i += 256) {
        int b = i / 50, k = i - b * 50;
        pw_s[b * 51 + k] = pw[((size_t)b * S_LEN + s) * W5 + k];
    }
    for (int i = t; i < 128 * 50; i += 256) {
        int e = i / 50, k = i - e * 50;
        we_s[e * 51 + k] = Wemb[e * 50 + k];
    }
    __syncthreads();

    const int e = t & 127, bh = t >> 7;
    float wreg[50];
#pragma unroll
    for (int k = 0; k < 50; k++) wreg[k] = we_s[e * 51 + k];
    const float be = bemb[e];
    float* outp = g_emb + (size_t)s * (B_N * E_N);
    for (int bb = 0; bb < 32; bb++) {
        int b = bh * 32 + bb;
        float acc = be;
#pragma unroll
        for (int k = 0; k < 50; k++) acc = fmaf(pw_s[b * 51 + k], wreg[k], acc);
        outp[b * 128 + e] = fmaxf(acc, 0.0f);
    }
}

// =============== Phase 1b: x_gates[s][b][g] = Wih @ emb^T + (bih+bhh) ===============
#define XP 68
#define TPCH 69
__global__ void __launch_bounds__(128) xgates_kernel(const float* __restrict__ Wih,
                                                     const float* __restrict__ bih,
                                                     const float* __restrict__ bhh) {
    extern __shared__ float sm[];
    float* wT = sm;                 // [e=128][g=64] pitch XP
    float* eT = sm + 128 * XP;      // [e=128][b=64] pitch XP
    float* tr = eT + 128 * XP;      // [b=64][g=64]  pitch TPCH
    const int s = blockIdx.y, gt = blockIdx.x;
    const int t = threadIdx.x;

    for (int i = t; i < 64 * 128; i += 128) {
        int e = i & 127, g = i >> 7;
        wT[e * XP + g] = Wih[((size_t)(gt * 64 + g)) * 128 + e];
    }
    const float* embp = g_emb + (size_t)s * (B_N * E_N);
    for (int i = t; i < 64 * 128; i += 128) {
        int e = i & 127, b = i >> 7;
        eT[e * XP + b] = embp[b * 128 + e];
    }
    __syncthreads();

    const int gq = t >> 4;
    const int bq = t & 15;
    float acc[8][4];
#pragma unroll
    for (int i = 0; i < 8; i++)
#pragma unroll
        for (int j = 0; j < 4; j++) acc[i][j] = 0.0f;

#pragma unroll 4
    for (int e = 0; e < 128; e++) {
        float4 w0 = *(float4*)&wT[e * XP + gq * 8];
        float4 w1 = *(float4*)&wT[e * XP + gq * 8 + 4];
        float4 hv = *(float4*)&eT[e * XP + bq * 4];
        float w[8] = {w0.x, w0.y, w0.z, w0.w, w1.x, w1.y, w1.z, w1.w};
        float x[4] = {hv.x, hv.y, hv.z, hv.w};
#pragma unroll
        for (int i = 0; i < 8; i++)
#pragma unroll
            for (int j = 0; j < 4; j++) acc[i][j] = fmaf(w[i], x[j], acc[i][j]);
    }

#pragma unroll
    for (int i = 0; i < 8; i++) {
        int gl = gq * 8 + i;
        int gg = gt * 64 + gl;
        float bs = bih[gg] + bhh[gg];
#pragma unroll
        for (int j = 0; j < 4; j++) tr[(bq * 4 + j) * TPCH + gl] = acc[i][j] + bs;
    }
    __syncthreads();

    float* xgp = g_xg + (size_t)s * (B_N * G_N);
    for (int idx = t; idx < 64 * 64; idx += 128) {
        int b = idx >> 6, g = idx & 63;
        xgp[(size_t)b * G_N + gt * 64 + g] = tr[b * TPCH + g];
    }
}

// =============== Phase 2: clustered LSTM scan — r4 skeleton, SCALAR engine ==========
// 16 clusters x 8 CTAs x 256 threads. Cluster cl owns batches 4cl..4cl+3.
// CTA rank owns hidden cols j = 32*rank..+31. Thread: rg=t>>3 (j-local), kq=t&7 (k-split).
// Inner engine: plain fmaf, scalar weights/accumulators — no 64-bit pairs, no asm.
__global__ void __launch_bounds__(256, 1) __cluster_dims__(8, 1, 1)
lstm_kernel(const float* __restrict__ Whh,
            const float* __restrict__ h0,
            const float* __restrict__ c0) {
    __shared__ float4 h_s[2][256];          // [buf][k] x 4 batches (16B k-stride: conflict-free)

    cg::cluster_group cluster = cg::this_cluster();
    const int rank = (int)cluster.block_rank();
    const int cl   = (int)(blockIdx.x >> 3);
    const int t    = threadIdx.x;
    const int kq   = t & 7;
    const int rg   = t >> 3;
    const int jg   = rank * 32 + rg;

    // register-resident W_hh: 4 gates x 32 k-slice scalars for column jg
    float wi[32], wf[32], wg[32], wo[32];
#pragma unroll
    for (int kk = 0; kk < 32; kk++) {
        int k = (kk << 3) | kq;
        wi[kk] = Whh[(size_t)(0 * 256 + jg) * 256 + k];
        wf[kk] = Whh[(size_t)(1 * 256 + jg) * 256 + k];
        wg[kk] = Whh[(size_t)(2 * 256 + jg) * 256 + k];
        wo[kk] = Whh[(size_t)(3 * 256 + jg) * 256 + k];
    }

    // DSMEM peer pointers (includes self)
    float4* peer[8];
#pragma unroll
    for (int p = 0; p < 8; p++) peer[p] = cluster.map_shared_rank(&h_s[0][0], p);

    // init h buffer 0 from h0 ([b][j] layout)
    h_s[0][t] = make_float4(h0[(4 * cl + 0) * 256 + t],
                            h0[(4 * cl + 1) * 256 + t],
                            h0[(4 * cl + 2) * 256 + t],
                            h0[(4 * cl + 3) * 256 + t]);
    float c = 0.0f;
    if (kq < 4) c = c0[(4 * cl + kq) * 256 + jg];

    // prefetch x-gates for s=0
    float xgi = 0.f, xgf = 0.f, xgg = 0.f, xgo = 0.f;
    if (kq < 4) {
        const float* xp = g_xg + ((size_t)0 * B_N + (4 * cl + kq)) * G_N;
        xgi = xp[0 * 256 + jg]; xgf = xp[1 * 256 + jg];
        xgg = xp[2 * 256 + jg]; xgo = xp[3 * 256 + jg];
    }
    __syncthreads();
    asm volatile("barrier.cluster.arrive.aligned;" ::: "memory");
    asm volatile("barrier.cluster.wait.aligned;" ::: "memory");

    const int lane = t & 31;
    const int obase = lane & 24;            // octet base for gather shfl

    for (int s = 0; s < S_LEN; s++) {
        const float4* hb = h_s[s & 1];
        // 16 scalar accumulators: gate x batch
        float ai0=0,ai1=0,ai2=0,ai3=0, af0=0,af1=0,af2=0,af3=0;
        float ag0=0,ag1=0,ag2=0,ag3=0, ao0=0,ao1=0,ao2=0,ao3=0;
#pragma unroll
        for (int kk = 0; kk < 32; kk++) {
            float4 hv = hb[(kk << 3) | kq];
            float vi = wi[kk], vf = wf[kk], vg = wg[kk], vo = wo[kk];
            ai0 = fmaf(vi, hv.x, ai0); ai1 = fmaf(vi, hv.y, ai1);
            ai2 = fmaf(vi, hv.z, ai2); ai3 = fmaf(vi, hv.w, ai3);
            af0 = fmaf(vf, hv.x, af0); af1 = fmaf(vf, hv.y, af1);
            af2 = fmaf(vf, hv.z, af2); af3 = fmaf(vf, hv.w, af3);
            ag0 = fmaf(vg, hv.x, ag0); ag1 = fmaf(vg, hv.y, ag1);
            ag2 = fmaf(vg, hv.z, ag2); ag3 = fmaf(vg, hv.w, ag3);
            ao0 = fmaf(vo, hv.x, ao0); ao1 = fmaf(vo, hv.y, ao1);
            ao2 = fmaf(vo, hv.z, ao2); ao3 = fmaf(vo, hv.w, ao3);
        }

        // butterfly reduce over the 8 kq lanes (octet-local)
#pragma unroll
        for (int off = 1; off < 8; off <<= 1) {
            ai0 += __shfl_xor_sync(0xffffffffu, ai0, off);
            ai1 += __shfl_xor_sync(0xffffffffu, ai1, off);
            ai2 += __shfl_xor_sync(0xffffffffu, ai2, off);
            ai3 += __shfl_xor_sync(0xffffffffu, ai3, off);
            af0 += __shfl_xor_sync(0xffffffffu, af0, off);
            af1 += __shfl_xor_sync(0xffffffffu, af1, off);
            af2 += __shfl_xor_sync(0xffffffffu, af2, off);
            af3 += __shfl_xor_sync(0xffffffffu, af3, off);
            ag0 += __shfl_xor_sync(0xffffffffu, ag0, off);
            ag1 += __shfl_xor_sync(0xffffffffu, ag1, off);
            ag2 += __shfl_xor_sync(0xffffffffu, ag2, off);
            ag3 += __shfl_xor_sync(0xffffffffu, ag3, off);
            ao0 += __shfl_xor_sync(0xffffffffu, ao0, off);
            ao1 += __shfl_xor_sync(0xffffffffu, ao1, off);
            ao2 += __shfl_xor_sync(0xffffffffu, ao2, off);
            ao3 += __shfl_xor_sync(0xffffffffu, ao3, off);
        }

        // lanes kq=0..3 update batch b=kq for column jg
        float hval = 0.0f;
        if (kq < 4) {
            float si = (kq == 0) ? ai0 : (kq == 1) ? ai1 : (kq == 2) ? ai2 : ai3;
            float sf = (kq == 0) ? af0 : (kq == 1) ? af1 : (kq == 2) ? af2 : af3;
            float sg = (kq == 0) ? ag0 : (kq == 1) ? ag1 : (kq == 2) ? ag2 : ag3;
            float so = (kq == 0) ? ao0 : (kq == 1) ? ao1 : (kq == 2) ? ao2 : ao3;
            float iv = sigf(si + xgi);
            float fv = sigf(sf + xgf);
            float gv = tanhf_fast(sg + xgg);
            float ov = sigf(so + xgo);
            c = fv * c + iv * gv;
            hval = ov * tanhf_fast(c);
        }

        // gather 4 batch-values into kq==0 lane, broadcast h to all 8 CTAs
        float hx = __shfl_sync(0xffffffffu, hval, obase + 0);
        float hy = __shfl_sync(0xffffffffu, hval, obase + 1);
        float hz = __shfl_sync(0xffffffffu, hval, obase + 2);
        float hw = __shfl_sync(0xffffffffu, hval, obase + 3);
        float4 o4 = make_float4(hx, hy, hz, hw);
        if (kq == 0) {
            int slot = (((s + 1) & 1) << 8) + jg;
#pragma unroll
            for (int p = 0; p < 8; p++) peer[p][slot] = o4;
        }

        asm volatile("barrier.cluster.arrive.aligned;" ::: "memory");

        // g_hs store after arrive: only the post-kernel readout reads it
        if (kq == 0)
            *(float4*)&g_hs[(((size_t)s * 16 + cl) * 256 + jg) * 4] = o4;

        // prefetch next step's x-gates while waiting
        if (kq < 4 && s + 1 < S_LEN) {
            const float* xp = g_xg + ((size_t)(s + 1) * B_N + (4 * cl + kq)) * G_N;
            xgi = xp[0 * 256 + jg]; xgf = xp[1 * 256 + jg];
            xgg = xp[2 * 256 + jg]; xgo = xp[3 * 256 + jg];
        }

        asm volatile("barrier.cluster.wait.aligned;" ::: "memory");
    }

    // teardown: no CTA exits while peers might still store into its smem
    asm volatile("barrier.cluster.arrive.aligned;" ::: "memory");
    asm volatile("barrier.cluster.wait.aligned;" ::: "memory");
}

// =============== Phase 3: readout, g_hs is [s][cl][j][b4] ===============
__global__ void __launch_bounds__(256) readout_kernel(const float* __restrict__ Wout,
                                                      const float* __restrict__ bout,
                                                      float* __restrict__ y) {
    __shared__ float part[4][64];
    const int s = blockIdx.x;
    const int t = threadIdx.x;
    const int p = t & 63;          // p == global batch (cl = p>>2, bq = p&3)
    const int q = t >> 6;          // j-quarter
    const float* hp = g_hs + (((size_t)s * 16 + (p >> 2)) * 256) * 4 + (p & 3);
    float acc = 0.0f;
#pragma unroll 8
    for (int j = q * 64; j < q * 64 + 64; j++)
        acc = fmaf(hp[(size_t)j * 4], Wout[j], acc);
    part[q][p] = acc;
    __syncthreads();
    if (t < 64) {
        float v = part[0][t] + part[1][t] + part[2][t] + part[3][t] + bout[0];
        y[s * 64 + t] = sigf(v);
    }
}

// =============== host launcher ===============
extern "C" void kernel_launch(void* const* d_in, const int* in_sizes, int n_in,
                              void* d_out, int out_size) {
    const float* pw   = (const float*)d_in[0];
    const float* Wemb = (const float*)d_in[1];
    const float* bemb = (const float*)d_in[2];
    const float* Wih  = (const float*)d_in[3];
    const float* Whh  = (const float*)d_in[4];
    const float* bih  = (const float*)d_in[5];
    const float* bhh  = (const float*)d_in[6];
    const float* Wout = (const float*)d_in[7];
    const float* bout = (const float*)d_in[8];
    const float* h0   = (const float*)d_in[9];
    const float* c0   = (const float*)d_in[10];
    float* y = (float*)d_out;

    static bool attrs_set = false;
    const int xg_smem = (2 * 128 * XP + 64 * TPCH) * (int)sizeof(float);
    if (!attrs_set) {
        cudaFuncSetAttribute(xgates_kernel, cudaFuncAttributeMaxDynamicSharedMemorySize, xg_smem);
        attrs_set = true;
    }

    emb_kernel<<<S_LEN, 256>>>(pw, Wemb, bemb);
    xgates_kernel<<<dim3(16, S_LEN), 128, xg_smem>>>(Wih, bih, bhh);
    lstm_kernel<<<128, 256>>>(Whh, h0, c0);
    readout_kernel<<<S_LEN, 256>>>(Wout, bout, y);
}

// round 14
// speedup vs baseline: 1.3514x; 1.3514x over previous
#include <cuda_runtime.h>
#include <cuda_bf16.h>
#include <cooperative_groups.h>
#include <cstdint>

namespace cg = cooperative_groups;

#define S_LEN 2048
#define B_N   64
#define W5    50
#define E_N   128
#define H_N   256
#define G_N   1024

typedef unsigned long long ull;

// ---------------- static device scratch (allocation-free) ----------------
__device__ float g_emb[(size_t)S_LEN * B_N * E_N];      // [s][b][e]
__device__ float g_xg [(size_t)S_LEN * B_N * G_N];      // [s][b][g]
__device__ float g_hs [(size_t)S_LEN * 16 * H_N * 4];   // [s][cl][j][b4]

__device__ __forceinline__ float sigf(float x) { return 1.0f / (1.0f + __expf(-x)); }
__device__ __forceinline__ float tanhf_fast(float x) {
    float e = __expf(2.0f * x);
    return 1.0f - 2.0f / (e + 1.0f);   // safe at +/-inf
}

__device__ __forceinline__ ull pack2(float lo, float hi) {
    ull r; asm("mov.b64 %0, {%1, %2};" : "=l"(r) : "f"(lo), "f"(hi)); return r;
}
__device__ __forceinline__ void unpack2(ull v, float& lo, float& hi) {
    asm("mov.b64 {%0, %1}, %2;" : "=f"(lo), "=f"(hi) : "l"(v));
}
__device__ __forceinline__ void fma2(ull& d, ull a, ull b) {
    asm("fma.rn.f32x2 %0, %1, %2, %0;" : "+l"(d) : "l"(a), "l"(b));
}
__device__ __forceinline__ ull add2(ull a, ull b) {
    ull r; asm("add.rn.f32x2 %0, %1, %2;" : "=l"(r) : "l"(a), "l"(b)); return r;
}

// =============== Phase 1a: emb = relu(pw @ Wemb^T + bemb) ===============
__global__ void __launch_bounds__(256) emb_kernel(const float* __restrict__ pw,
                                                  const float* __restrict__ Wemb,
                                                  const float* __restrict__ bemb) {
    __shared__ float pw_s[64 * 51];
    __shared__ float we_s[128 * 51];
    const int s = blockIdx.x;
    const int t = threadIdx.x;

    for (int i = t; i < 64 * 50; i += 256) {
        int b = i / 50, k = i - b * 50;
        pw_s[b * 51 + k] = pw[((size_t)b * S_LEN + s) * W5 + k];
    }
    for (int i = t; i < 128 * 50; i += 256) {
        int e = i / 50, k = i - e * 50;
        we_s[e * 51 + k] = Wemb[e * 50 + k];
    }
    __syncthreads();

    const int e = t & 127, bh = t >> 7;
    float wreg[50];
#pragma unroll
    for (int k = 0; k < 50; k++) wreg[k] = we_s[e * 51 + k];
    const float be = bemb[e];
    float* outp = g_emb + (size_t)s * (B_N * E_N);
    for (int bb = 0; bb < 32; bb++) {
        int b = bh * 32 + bb;
        float acc = be;
#pragma unroll
        for (int k = 0; k < 50; k++) acc = fmaf(pw_s[b * 51 + k], wreg[k], acc);
        outp[b * 128 + e] = fmaxf(acc, 0.0f);
    }
}

// =============== Phase 1b: x_gates[s][b][g] = Wih @ emb^T + (bih+bhh) ===============
#define XP 68
#define TPCH 69
__global__ void __launch_bounds__(128) xgates_kernel(const float* __restrict__ Wih,
                                                     const float* __restrict__ bih,
                                                     const float* __restrict__ bhh) {
    extern __shared__ float sm[];
    float* wT = sm;                 // [e=128][g=64] pitch XP
    float* eT = sm + 128 * XP;      // [e=128][b=64] pitch XP
    float* tr = eT + 128 * XP;      // [b=64][g=64]  pitch TPCH
    const int s = blockIdx.y, gt = blockIdx.x;
    const int t = threadIdx.x;

    for (int i = t; i < 64 * 128; i += 128) {
        int e = i & 127, g = i >> 7;
        wT[e * XP + g] = Wih[((size_t)(gt * 64 + g)) * 128 + e];
    }
    const float* embp = g_emb + (size_t)s * (B_N * E_N);
    for (int i = t; i < 64 * 128; i += 128) {
        int e = i & 127, b = i >> 7;
        eT[e * XP + b] = embp[b * 128 + e];
    }
    __syncthreads();

    const int gq = t >> 4;
    const int bq = t & 15;
    float acc[8][4];
#pragma unroll
    for (int i = 0; i < 8; i++)
#pragma unroll
        for (int j = 0; j < 4; j++) acc[i][j] = 0.0f;

#pragma unroll 4
    for (int e = 0; e < 128; e++) {
        float4 w0 = *(float4*)&wT[e * XP + gq * 8];
        float4 w1 = *(float4*)&wT[e * XP + gq * 8 + 4];
        float4 hv = *(float4*)&eT[e * XP + bq * 4];
        float w[8] = {w0.x, w0.y, w0.z, w0.w, w1.x, w1.y, w1.z, w1.w};
        float x[4] = {hv.x, hv.y, hv.z, hv.w};
#pragma unroll
        for (int i = 0; i < 8; i++)
#pragma unroll
            for (int j = 0; j < 4; j++) acc[i][j] = fmaf(w[i], x[j], acc[i][j]);
    }

#pragma unroll
    for (int i = 0; i < 8; i++) {
        int gl = gq * 8 + i;
        int gg = gt * 64 + gl;
        float bs = bih[gg] + bhh[gg];
#pragma unroll
        for (int j = 0; j < 4; j++) tr[(bq * 4 + j) * TPCH + gl] = acc[i][j] + bs;
    }
    __syncthreads();

    float* xgp = g_xg + (size_t)s * (B_N * G_N);
    for (int idx = t; idx < 64 * 64; idx += 128) {
        int b = idx >> 6, g = idx & 63;
        xgp[(size_t)b * G_N + gt * 64 + g] = tr[b * TPCH + g];
    }
}

// =============== Phase 2: clustered LSTM scan — r4 engine, 512 threads ===============
// 16 clusters x 8 CTAs x 512 threads. Cluster cl owns batches 4cl..4cl+3.
// CTA rank owns hidden cols j = 32*rank..+31.
// Thread: rg = t>>4 (j-local 0..31), kq = t&15 (16-way k-split).
// Same f32x2 engine as the 11.29ms champion; 2x warp contexts for latency hiding.
__global__ void __launch_bounds__(512, 1) __cluster_dims__(8, 1, 1)
lstm_kernel(const float* __restrict__ Whh,
            const float* __restrict__ h0,
            const float* __restrict__ c0) {
    __shared__ float4 h_s[2][256];          // [buf][k] x 4 batches

    cg::cluster_group cluster = cg::this_cluster();
    const int rank = (int)cluster.block_rank();
    const int cl   = (int)(blockIdx.x >> 3);
    const int t    = threadIdx.x;
    const int kq   = t & 15;
    const int rg   = t >> 4;
    const int jg   = rank * 32 + rg;

    // register-resident W_hh pairs: (Wi,Wf),(Wg,Wo) for column jg, k = 16*kk+kq
    ull wif[16], wgo[16];
#pragma unroll
    for (int kk = 0; kk < 16; kk++) {
        int k = (kk << 4) | kq;
        wif[kk] = pack2(Whh[(size_t)(0 * 256 + jg) * 256 + k],
                        Whh[(size_t)(1 * 256 + jg) * 256 + k]);
        wgo[kk] = pack2(Whh[(size_t)(2 * 256 + jg) * 256 + k],
                        Whh[(size_t)(3 * 256 + jg) * 256 + k]);
    }

    // DSMEM peer pointers (includes self)
    float4* peer[8];
#pragma unroll
    for (int p = 0; p < 8; p++) peer[p] = cluster.map_shared_rank(&h_s[0][0], p);

    // init h buffer 0 from h0 ([b][j] layout)
    if (t < 256) {
        h_s[0][t] = make_float4(h0[(4 * cl + 0) * 256 + t],
                                h0[(4 * cl + 1) * 256 + t],
                                h0[(4 * cl + 2) * 256 + t],
                                h0[(4 * cl + 3) * 256 + t]);
    }
    float c = 0.0f;
    if (kq < 4) c = c0[(4 * cl + kq) * 256 + jg];

    // prefetch x-gates for s=0
    float xgi = 0.f, xgf = 0.f, xgg = 0.f, xgo = 0.f;
    if (kq < 4) {
        const float* xp = g_xg + ((size_t)0 * B_N + (4 * cl + kq)) * G_N;
        xgi = xp[0 * 256 + jg]; xgf = xp[1 * 256 + jg];
        xgg = xp[2 * 256 + jg]; xgo = xp[3 * 256 + jg];
    }
    __syncthreads();
    asm volatile("barrier.cluster.arrive.aligned;" ::: "memory");
    asm volatile("barrier.cluster.wait.aligned;" ::: "memory");

    const int lane = t & 31;
    const int gbase = lane & 16;            // 16-lane group base for gather shfl

    for (int s = 0; s < S_LEN; s++) {
        const float4* hb = h_s[s & 1];
        ull aif0 = 0, aif1 = 0, aif2 = 0, aif3 = 0;
        ull ago0 = 0, ago1 = 0, ago2 = 0, ago3 = 0;
#pragma unroll
        for (int kk = 0; kk < 16; kk++) {
            float4 hv = hb[(kk << 4) | kq];
            ull b0 = pack2(hv.x, hv.x), b1 = pack2(hv.y, hv.y);
            ull b2 = pack2(hv.z, hv.z), b3 = pack2(hv.w, hv.w);
            fma2(aif0, wif[kk], b0); fma2(ago0, wgo[kk], b0);
            fma2(aif1, wif[kk], b1); fma2(ago1, wgo[kk], b1);
            fma2(aif2, wif[kk], b2); fma2(ago2, wgo[kk], b2);
            fma2(aif3, wif[kk], b3); fma2(ago3, wgo[kk], b3);
        }

        // butterfly reduce over the 16 kq lanes
#pragma unroll
        for (int off = 1; off < 16; off <<= 1) {
            aif0 = add2(aif0, __shfl_xor_sync(0xffffffffu, aif0, off));
            aif1 = add2(aif1, __shfl_xor_sync(0xffffffffu, aif1, off));
            aif2 = add2(aif2, __shfl_xor_sync(0xffffffffu, aif2, off));
            aif3 = add2(aif3, __shfl_xor_sync(0xffffffffu, aif3, off));
            ago0 = add2(ago0, __shfl_xor_sync(0xffffffffu, ago0, off));
            ago1 = add2(ago1, __shfl_xor_sync(0xffffffffu, ago1, off));
            ago2 = add2(ago2, __shfl_xor_sync(0xffffffffu, ago2, off));
            ago3 = add2(ago3, __shfl_xor_sync(0xffffffffu, ago3, off));
        }

        // lanes kq=0..3 update batch b=kq for column jg
        float hval = 0.0f;
        if (kq < 4) {
            ull aif = (kq == 0) ? aif0 : (kq == 1) ? aif1 : (kq == 2) ? aif2 : aif3;
            ull ago = (kq == 0) ? ago0 : (kq == 1) ? ago1 : (kq == 2) ? ago2 : ago3;
            float si, sf, sg, so;
            unpack2(aif, si, sf);
            unpack2(ago, sg, so);
            float iv = sigf(si + xgi);
            float fv = sigf(sf + xgf);
            float gv = tanhf_fast(sg + xgg);
            float ov = sigf(so + xgo);
            c = fv * c + iv * gv;
            hval = ov * tanhf_fast(c);
        }

        // gather 4 batch-values into kq==0 lane, broadcast h to all 8 CTAs
        float hx = __shfl_sync(0xffffffffu, hval, gbase + 0);
        float hy = __shfl_sync(0xffffffffu, hval, gbase + 1);
        float hz = __shfl_sync(0xffffffffu, hval, gbase + 2);
        float hw = __shfl_sync(0xffffffffu, hval, gbase + 3);
        float4 o4 = make_float4(hx, hy, hz, hw);
        if (kq == 0) {
            int slot = (((s + 1) & 1) << 8) + jg;
#pragma unroll
            for (int p = 0; p < 8; p++) peer[p][slot] = o4;
        }

        asm volatile("barrier.cluster.arrive.aligned;" ::: "memory");

        // g_hs store after arrive: only the post-kernel readout reads it
        if (kq == 0)
            *(float4*)&g_hs[(((size_t)s * 16 + cl) * 256 + jg) * 4] = o4;

        // prefetch next step's x-gates while waiting
        if (kq < 4 && s + 1 < S_LEN) {
            const float* xp = g_xg + ((size_t)(s + 1) * B_N + (4 * cl + kq)) * G_N;
            xgi = xp[0 * 256 + jg]; xgf = xp[1 * 256 + jg];
            xgg = xp[2 * 256 + jg]; xgo = xp[3 * 256 + jg];
        }

        asm volatile("barrier.cluster.wait.aligned;" ::: "memory");
    }

    // teardown: no CTA exits while peers might still store into its smem
    asm volatile("barrier.cluster.arrive.aligned;" ::: "memory");
    asm volatile("barrier.cluster.wait.aligned;" ::: "memory");
}

// =============== Phase 3: readout, g_hs is [s][cl][j][b4] ===============
__global__ void __launch_bounds__(256) readout_kernel(const float* __restrict__ Wout,
                                                      const float* __restrict__ bout,
                                                      float* __restrict__ y) {
    __shared__ float part[4][64];
    const int s = blockIdx.x;
    const int t = threadIdx.x;
    const int p = t & 63;          // p == global batch (cl = p>>2, bq = p&3)
    const int q = t >> 6;          // j-quarter
    const float* hp = g_hs + (((size_t)s * 16 + (p >> 2)) * 256) * 4 + (p & 3);
    float acc = 0.0f;
#pragma unroll 8
    for (int j = q * 64; j < q * 64 + 64; j++)
        acc = fmaf(hp[(size_t)j * 4], Wout[j], acc);
    part[q][p] = acc;
    __syncthreads();
    if (t < 64) {
        float v = part[0][t] + part[1][t] + part[2][t] + part[3][t] + bout[0];
        y[s * 64 + t] = sigf(v);
    }
}

// =============== host launcher ===============
extern "C" void kernel_launch(void* const* d_in, const int* in_sizes, int n_in,
                              void* d_out, int out_size) {
    const float* pw   = (const float*)d_in[0];
    const float* Wemb = (const float*)d_in[1];
    const float* bemb = (const float*)d_in[2];
    const float* Wih  = (const float*)d_in[3];
    const float* Whh  = (const float*)d_in[4];
    const float* bih  = (const float*)d_in[5];
    const float* bhh  = (const float*)d_in[6];
    const float* Wout = (const float*)d_in[7];
    const float* bout = (const float*)d_in[8];
    const float* h0   = (const float*)d_in[9];
    const float* c0   = (const float*)d_in[10];
    float* y = (float*)d_out;

    static bool attrs_set = false;
    const int xg_smem = (2 * 128 * XP + 64 * TPCH) * (int)sizeof(float);
    if (!attrs_set) {
        cudaFuncSetAttribute(xgates_kernel, cudaFuncAttributeMaxDynamicSharedMemorySize, xg_smem);
        attrs_set = true;
    }

    emb_kernel<<<S_LEN, 256>>>(pw, Wemb, bemb);
    xgates_kernel<<<dim3(16, S_LEN), 128, xg_smem>>>(Wih, bih, bhh);
    lstm_kernel<<<128, 512>>>(Whh, h0, c0);
    readout_kernel<<<S_LEN, 256>>>(Wout, bout, y);
}